// round 13
// baseline (speedup 1.0000x reference)
#include <cuda_runtime.h>
#include <cstddef>
#include <cstdint>

// Problem constants (fixed by the reference):
//   B_PAIRS=2048 pairs, each pair = 44 ligand nodes + 300 protein nodes (stride 344)
//   Only the ligand segment sums (even segments) feed the MLP.
//   MLP: 128 ->256 relu -> 128 relu -> 64 relu -> 1
#define B_PAIRS 2048
#define LIG     44
#define STRIDE  344
#define F_IN    128
#define N0      256
#define N1      128
#define N2      64
#define RTILE   8          // pairs per MLP block -> grid 256
#define THREADS 256

typedef unsigned long long u64;

// 1 MB scratch for the per-pair feature sums.
__device__ float g_xs[B_PAIRS * F_IN];

// ---------------- packed fp32x2 helpers (sm_103a FFMA2) --------------------
#define PACK_F32X2(d, lo, hi) \
    asm("mov.b64 %0, {%1, %2};" : "=l"(d) : "f"(lo), "f"(hi))
#define UNPACK_F32X2(lo, hi, v) \
    asm("mov.b64 {%0, %1}, %2;" : "=f"(lo), "=f"(hi) : "l"(v))
#define FMA_F32X2(d, a, b, c) \
    asm("fma.rn.f32x2 %0, %1, %2, %3;" : "=l"(d) : "l"(a), "l"(b), "l"(c))
#define ADD_F32X2(d, a, b) \
    asm("add.rn.f32x2 %0, %1, %2;" : "=l"(d) : "l"(a), "l"(b))

// ---------------- smem/mbarrier/TMA-1D helpers ------------------------------
__device__ __forceinline__ uint32_t smem_u32(const void* p) {
    uint32_t a;
    asm("{ .reg .u64 t; cvta.to.shared.u64 t, %1; cvt.u32.u64 %0, t; }"
        : "=r"(a) : "l"(p));
    return a;
}
__device__ __forceinline__ void mbar_init(uint32_t mbar) {
    asm volatile("mbarrier.init.shared.b64 [%0], %1;" :: "r"(mbar), "r"(1u)
                 : "memory");
}
__device__ __forceinline__ void mbar_wait(uint32_t mbar, uint32_t parity) {
    asm volatile(
        "{\n\t.reg .pred P;\n"
        "W_%=:\n\t"
        "mbarrier.try_wait.parity.acquire.cta.shared::cta.b64 P, [%0], %1, 0x989680;\n\t"
        "@P bra D_%=;\n\t"
        "bra W_%=;\n"
        "D_%=:\n\t}"
        :: "r"(mbar), "r"(parity) : "memory");
}
// 1D bulk global->shared with transaction-count completion (single thread).
__device__ __forceinline__ void tma1d(uint32_t dst, const void* src,
                                      uint32_t bytes, uint32_t mbar) {
    asm volatile("mbarrier.arrive.expect_tx.shared.b64 _, [%0], %1;"
                 :: "r"(mbar), "r"(bytes) : "memory");
    asm volatile(
        "cp.async.bulk.shared::cluster.global.mbarrier::complete_tx::bytes "
        "[%0], [%1], %2, [%3];"
        :: "r"(dst), "l"(src), "r"(bytes), "r"(mbar) : "memory");
}

// ============================================================================
// Kernel A: ligand segment sum. One block per pair (hot 46 MB L2-resident).
// ============================================================================
__global__ void __launch_bounds__(THREADS)
seg_sum_kernel(const float* __restrict__ features)
{
    __shared__ float4 part[8][32];
    const int tid  = threadIdx.x;
    const int pair = blockIdx.x;
    const int c4   = tid & 31;
    const int g    = tid >> 5;

    const float4* src = reinterpret_cast<const float4*>(features)
                      + (size_t)pair * STRIDE * (F_IN / 4) + c4;
    float4 acc = make_float4(0.f, 0.f, 0.f, 0.f);
#pragma unroll
    for (int r = g; r < LIG; r += 8) {
        float4 v = __ldcs(src + (size_t)r * (F_IN / 4));
        acc.x += v.x; acc.y += v.y; acc.z += v.z; acc.w += v.w;
    }
    part[g][c4] = acc;
    __syncthreads();

    if (tid < 32) {
        float4 s = part[0][tid];
#pragma unroll
        for (int gg = 1; gg < 8; ++gg) {
            float4 v = part[gg][tid];
            s.x += v.x; s.y += v.y; s.z += v.z; s.w += v.w;
        }
        reinterpret_cast<float4*>(g_xs)[pair * (F_IN / 4) + tid] = s;
    }
}

// ============================================================================
// Kernel B: 4-layer MLP, RTILE=8, grid=256, 256 threads, TMA-staged weights.
// Weights stream through a 2 x 32KB SMEM ring via cp.async.bulk; inner loops
// are pure LDS + FFMA2 (no global loads at all).
//   L0: ct=colpair(128) x rh=row-half(2)  -> acc 4 u64, full K, no reduction
//   L1: ct=colpair(64)  x rq=row-pair(4)  -> acc 2 u64, full K, no reduction
//   L2: ct=colpair(32) x rq(4) x kh(2)    -> acc 2 u64, one partner reduction
// ============================================================================
// Dynamic SMEM layout (bytes):
#define OFF_WBUF   0          // 2 x 32768
#define OFF_XS     65536      // 128*8*4   = 4096
#define OFF_H0     69632      // 256*8*4   = 8192
#define OFF_H1     77824      // 128*8*4   = 4096
#define OFF_H2     81920      // 64*8*4    = 2048
#define OFF_PB     83968      // 2048 partials
#define OFF_MBAR   86016      // 2 x 8
#define SMEM_TOTAL 86144

__global__ void __launch_bounds__(THREADS)
mlp_kernel(const float* __restrict__ W0, const float* __restrict__ b0,
           const float* __restrict__ W1, const float* __restrict__ b1,
           const float* __restrict__ W2, const float* __restrict__ b2,
           const float* __restrict__ Wout, const float* __restrict__ bout,
           float* __restrict__ out)
{
    extern __shared__ __align__(16) char smem[];
    float* wbuf0 = reinterpret_cast<float*>(smem + OFF_WBUF);
    float* wbuf1 = reinterpret_cast<float*>(smem + OFF_WBUF + 32768);
    u64*   xsP   = reinterpret_cast<u64*>(smem + OFF_XS);   // [k*4 + rp]
    u64*   h0P   = reinterpret_cast<u64*>(smem + OFF_H0);
    u64*   h1P   = reinterpret_cast<u64*>(smem + OFF_H1);
    float* h2T   = reinterpret_cast<float*>(smem + OFF_H2); // [col*8 + row]
    u64*   pbuf  = reinterpret_cast<u64*>(smem + OFF_PB);

    const uint32_t mb0 = smem_u32(smem + OFF_MBAR);
    const uint32_t mb1 = mb0 + 8;
    const uint32_t wb0 = smem_u32(wbuf0);
    const uint32_t wb1 = smem_u32(wbuf1);

    const int tid = threadIdx.x;
    const int p0  = blockIdx.x * RTILE;

    if (tid == 0) { mbar_init(mb0); mbar_init(mb1); }
    __syncthreads();

    // Prologue: prefetch W0 chunks 0,1 (32 rows x 256 cols = 32 KB each).
    if (tid == 0) {
        tma1d(wb0, W0,             32768, mb0);
        tma1d(wb1, W0 + 32 * N0,   32768, mb1);
    }

    // Load 8 summed rows into raw row-pair layout: xsP[k*4 + rp].
    {
        const int pp = tid & 7;
        const int c4 = tid >> 3;                 // 0..31
        float4 v = reinterpret_cast<const float4*>(g_xs)
                       [(size_t)(p0 + pp) * (F_IN / 4) + c4];
        float* xf = reinterpret_cast<float*>(xsP);
        xf[(c4 * 4 + 0) * 8 + pp] = v.x;
        xf[(c4 * 4 + 1) * 8 + pp] = v.y;
        xf[(c4 * 4 + 2) * 8 + pp] = v.z;
        xf[(c4 * 4 + 3) * 8 + pp] = v.w;
    }
    __syncthreads();

    int ph0 = 0, ph1 = 0;

    // ======== Layer 0: [8,128]@[128,256]+b relu ============================
    {
        const int ct = tid & 127;                // cols 2ct, 2ct+1
        const int rh = tid >> 7;                 // rows 4rh..4rh+3
        u64 acc[4];                              // [col][row-pair]
#pragma unroll
        for (int i = 0; i < 4; ++i) acc[i] = 0ull;

#pragma unroll
        for (int c = 0; c < 4; ++c) {            // 4 chunks x 32 k
            const float* wb = (c & 1) ? wbuf1 : wbuf0;
            if (c & 1) { mbar_wait(mb1, ph1 & 1); ph1++; }
            else       { mbar_wait(mb0, ph0 & 1); ph0++; }
#pragma unroll 8
            for (int kk = 0; kk < 32; ++kk) {
                float2 wv = *reinterpret_cast<const float2*>(
                                wb + kk * N0 + 2 * ct);
                u64 wd0, wd1;
                PACK_F32X2(wd0, wv.x, wv.x);
                PACK_F32X2(wd1, wv.y, wv.y);
                ulonglong2 a = *reinterpret_cast<const ulonglong2*>(
                                   &xsP[(c * 32 + kk) * 4 + 2 * rh]);
                FMA_F32X2(acc[0], a.x, wd0, acc[0]);
                FMA_F32X2(acc[1], a.y, wd0, acc[1]);
                FMA_F32X2(acc[2], a.x, wd1, acc[2]);
                FMA_F32X2(acc[3], a.y, wd1, acc[3]);
            }
            __syncthreads();                     // all reads of buffer done
            if (tid == 0) {
                if (c == 0) tma1d(wb0, W0 + 64 * N0, 32768, mb0);
                if (c == 1) tma1d(wb1, W0 + 96 * N0, 32768, mb1);
                if (c == 2) tma1d(wb0, W1,           32768, mb0);  // W1 rows 0-63
                if (c == 3) tma1d(wb1, W1 + 64 * N1, 32768, mb1);  // rows 64-127
            }
        }
        float2 bv = *reinterpret_cast<const float2*>(b0 + 2 * ct);
        u64 bb0, bb1;
        PACK_F32X2(bb0, bv.x, bv.x);
        PACK_F32X2(bb1, bv.y, bv.y);
#pragma unroll
        for (int i = 0; i < 4; ++i) {
            ADD_F32X2(acc[i], acc[i], (i < 2) ? bb0 : bb1);
            float v0, v1; UNPACK_F32X2(v0, v1, acc[i]);
            PACK_F32X2(acc[i], fmaxf(v0, 0.f), fmaxf(v1, 0.f));
        }
        *reinterpret_cast<ulonglong2*>(&h0P[(2 * ct    ) * 4 + 2 * rh]) =
            make_ulonglong2(acc[0], acc[1]);
        *reinterpret_cast<ulonglong2*>(&h0P[(2 * ct + 1) * 4 + 2 * rh]) =
            make_ulonglong2(acc[2], acc[3]);
    }
    __syncthreads();

    // ======== Layer 1: [8,256]@[256,128]+b relu ============================
    {
        const int ct = tid & 63;                 // cols 2ct, 2ct+1
        const int rq = tid >> 6;                 // row-pair rq (rows 2rq,2rq+1)
        u64 acc0 = 0ull, acc1 = 0ull;

#pragma unroll
        for (int c = 0; c < 4; ++c) {            // 4 chunks x 64 k
            const float* wb = (c & 1) ? wbuf1 : wbuf0;
            if (c & 1) { mbar_wait(mb1, ph1 & 1); ph1++; }
            else       { mbar_wait(mb0, ph0 & 1); ph0++; }
#pragma unroll 8
            for (int kk = 0; kk < 64; ++kk) {
                float2 wv = *reinterpret_cast<const float2*>(
                                wb + kk * N1 + 2 * ct);
                u64 wd0, wd1;
                PACK_F32X2(wd0, wv.x, wv.x);
                PACK_F32X2(wd1, wv.y, wv.y);
                u64 a = h0P[(c * 64 + kk) * 4 + rq];
                FMA_F32X2(acc0, a, wd0, acc0);
                FMA_F32X2(acc1, a, wd1, acc1);
            }
            __syncthreads();
            if (tid == 0) {
                if (c == 0) tma1d(wb0, W1 + 128 * N1, 32768, mb0); // rows 128-191
                if (c == 1) tma1d(wb1, W1 + 192 * N1, 32768, mb1); // rows 192-255
                if (c == 2) tma1d(wb0, W2,            32768, mb0); // all of W2
            }
        }
        float2 bv = *reinterpret_cast<const float2*>(b1 + 2 * ct);
        u64 bb0, bb1;
        PACK_F32X2(bb0, bv.x, bv.x);
        PACK_F32X2(bb1, bv.y, bv.y);
        ADD_F32X2(acc0, acc0, bb0);
        ADD_F32X2(acc1, acc1, bb1);
        float v0, v1;
        UNPACK_F32X2(v0, v1, acc0);
        PACK_F32X2(acc0, fmaxf(v0, 0.f), fmaxf(v1, 0.f));
        UNPACK_F32X2(v0, v1, acc1);
        PACK_F32X2(acc1, fmaxf(v0, 0.f), fmaxf(v1, 0.f));
        h1P[(2 * ct    ) * 4 + rq] = acc0;
        h1P[(2 * ct + 1) * 4 + rq] = acc1;
    }
    __syncthreads();

    // ======== Layer 2: [8,128]@[128,64]+b relu =============================
    {
        const int ct = tid & 31;                 // cols 2ct, 2ct+1
        const int rq = (tid >> 5) & 3;           // row-pair
        const int kh = tid >> 7;                 // k half: rows 64kh..64kh+63
        u64 acc0 = 0ull, acc1 = 0ull;

        mbar_wait(mb0, ph0 & 1); ph0++;          // W2 buffer ready
#pragma unroll 8
        for (int kk = 0; kk < 64; ++kk) {
            float2 wv = *reinterpret_cast<const float2*>(
                            wbuf0 + (kh * 64 + kk) * N2 + 2 * ct);
            u64 wd0, wd1;
            PACK_F32X2(wd0, wv.x, wv.x);
            PACK_F32X2(wd1, wv.y, wv.y);
            u64 a = h1P[(kh * 64 + kk) * 4 + rq];
            FMA_F32X2(acc0, a, wd0, acc0);
            FMA_F32X2(acc1, a, wd1, acc1);
        }
        if (kh == 1) {
            pbuf[(ct * 4 + rq) * 2 + 0] = acc0;
            pbuf[(ct * 4 + rq) * 2 + 1] = acc1;
        }
        __syncthreads();
        if (kh == 0) {
            u64 q0 = pbuf[(ct * 4 + rq) * 2 + 0];
            u64 q1 = pbuf[(ct * 4 + rq) * 2 + 1];
            ADD_F32X2(acc0, acc0, q0);
            ADD_F32X2(acc1, acc1, q1);
            float2 bv = *reinterpret_cast<const float2*>(b2 + 2 * ct);
            u64 bb0, bb1;
            PACK_F32X2(bb0, bv.x, bv.x);
            PACK_F32X2(bb1, bv.y, bv.y);
            ADD_F32X2(acc0, acc0, bb0);
            ADD_F32X2(acc1, acc1, bb1);
            float v0, v1;
            UNPACK_F32X2(v0, v1, acc0);
            u64 s0; PACK_F32X2(s0, fmaxf(v0, 0.f), fmaxf(v1, 0.f));
            *reinterpret_cast<u64*>(&h2T[(2 * ct    ) * 8 + 2 * rq]) = s0;
            UNPACK_F32X2(v0, v1, acc1);
            u64 s1; PACK_F32X2(s1, fmaxf(v0, 0.f), fmaxf(v1, 0.f));
            *reinterpret_cast<u64*>(&h2T[(2 * ct + 1) * 8 + 2 * rq]) = s1;
        }
    }
    __syncthreads();

    // ======== Output: [8,64]@[64,1]+b  (8 warps = 8 rows) ===================
    {
        const int warp = tid >> 5;
        const int lane = tid & 31;
        float s = h2T[(2 * lane) * 8 + warp]     * Wout[2 * lane]
                + h2T[(2 * lane + 1) * 8 + warp] * Wout[2 * lane + 1];
#pragma unroll
        for (int o = 16; o > 0; o >>= 1)
            s += __shfl_down_sync(0xffffffffu, s, o);
        if (lane == 0)
            out[p0 + warp] = s + bout[0];
    }
}

// d_in order (metadata): [0] batch_num_nodes (unused), [1] features,
// [2] W0, [3] b0, [4] W1, [5] b1, [6] W2, [7] b2, [8] Wout, [9] bout.
extern "C" void kernel_launch(void* const* d_in, const int* in_sizes, int n_in,
                              void* d_out, int out_size)
{
    const float* features = (const float*)d_in[1];
    const float* W0   = (const float*)d_in[2];
    const float* b0   = (const float*)d_in[3];
    const float* W1   = (const float*)d_in[4];
    const float* b1   = (const float*)d_in[5];
    const float* W2   = (const float*)d_in[6];
    const float* b2   = (const float*)d_in[7];
    const float* Wout = (const float*)d_in[8];
    const float* bout = (const float*)d_in[9];
    float* out = (float*)d_out;

    cudaFuncSetAttribute(mlp_kernel,
                         cudaFuncAttributeMaxDynamicSharedMemorySize,
                         SMEM_TOTAL);

    seg_sum_kernel<<<B_PAIRS, THREADS>>>(features);
    mlp_kernel<<<B_PAIRS / RTILE, THREADS, SMEM_TOTAL>>>(
        W0, b0, W1, b1, W2, b2, Wout, bout, out);
}